// round 6
// baseline (speedup 1.0000x reference)
#include <cuda_runtime.h>
#include <math.h>

// Problem constants
#define NB_C   100000
#define CPAD   100096   // NB_C padded to a multiple of BN (=128); pad columns are 0
#define DIM    64
#define BATCH  1024
#define BM     64
#define BN     128

// ---------------------------------------------------------------------------
// Device scratch (static __device__ arrays: the sanctioned alloc-free scratch)
// ---------------------------------------------------------------------------
__device__ float g_Pn2T[DIM * CPAD];   // [d][c] = 2 * p_c[d] / max(||p_c||,1e-12); 0 in pad
__device__ float g_xsT [DIM * BATCH];  // [d][i] = xs[i][d]
__device__ float g_S   [BATCH];        // S_i = sum_c exp(2*x_i.p_c - 1)

// ---------------------------------------------------------------------------
// Packed fp32x2 helpers (sm_100+ FFMA2 path; PTX-only per SASS_QUICKREF)
// ---------------------------------------------------------------------------
__device__ __forceinline__ unsigned long long dup2(float x) {
    unsigned long long r;
    asm("mov.b64 %0, {%1, %1};" : "=l"(r) : "f"(x));
    return r;
}
__device__ __forceinline__ void ffma2(unsigned long long& d,
                                      unsigned long long a,
                                      unsigned long long b) {
    asm("fma.rn.f32x2 %0, %1, %2, %0;" : "+l"(d) : "l"(a), "l"(b));
}

// ---------------------------------------------------------------------------
// K1: transpose xs -> g_xsT (k-major) and zero g_S. 65536 threads.
// ---------------------------------------------------------------------------
__global__ void prep_kernel(const float* __restrict__ xs) {
    int g = blockIdx.x * 256 + threadIdx.x;      // 0 .. 65535
    int d = g & (DIM - 1);
    int i = g >> 6;
    g_xsT[d * BATCH + i] = xs[g];                // read coalesced, scatter write (2MB, trivial)
    if (g < BATCH) g_S[g] = 0.0f;
}

// ---------------------------------------------------------------------------
// K2: L2-normalize proxies (x2 folded in) and transpose to k-major g_Pn2T.
// One block = 64 proxy rows, 256 threads. Tiled via smem; coalesced both ways.
// ---------------------------------------------------------------------------
__global__ void norm_kernel(const float* __restrict__ proxies) {
    __shared__ float s[64][65];    // [c_local][d], padded
    __shared__ float sc[64];
    const int c0  = blockIdx.x * 64;
    const int tid = threadIdx.x;

    // Phase A: coalesced load of 64 rows x 64 cols (zero-fill past NB_C)
    #pragma unroll
    for (int it = 0; it < 4; ++it) {
        int g = tid + it * 256;                  // 1024 float4 tasks
        int r = g >> 4, dq = g & 15;
        int c = c0 + r;
        float4 v = make_float4(0.f, 0.f, 0.f, 0.f);
        if (c < NB_C) v = reinterpret_cast<const float4*>(proxies)[c * (DIM / 4) + dq];
        s[r][dq * 4 + 0] = v.x; s[r][dq * 4 + 1] = v.y;
        s[r][dq * 4 + 2] = v.z; s[r][dq * 4 + 3] = v.w;
    }
    __syncthreads();

    // Phase B: 4 threads per row compute sumsq -> scale = 2/max(norm,1e-12)
    {
        int r = tid >> 2, part = tid & 3;
        float ss = 0.f;
        #pragma unroll
        for (int j = 0; j < 16; ++j) { float v = s[r][part * 16 + j]; ss += v * v; }
        ss += __shfl_xor_sync(0xffffffffu, ss, 1);
        ss += __shfl_xor_sync(0xffffffffu, ss, 2);
        if (part == 0) sc[r] = 2.0f / fmaxf(sqrtf(ss), 1e-12f);
    }
    __syncthreads();

    // Phase C: scaled transpose store, coalesced along c (256B per half-warp)
    #pragma unroll
    for (int it = 0; it < 4; ++it) {
        int g = tid + it * 256;                  // d(64) x cq(16)
        int cq = g & 15, d = g >> 4;
        float4 o;
        o.x = s[cq * 4 + 0][d] * sc[cq * 4 + 0];
        o.y = s[cq * 4 + 1][d] * sc[cq * 4 + 1];
        o.z = s[cq * 4 + 2][d] * sc[cq * 4 + 2];
        o.w = s[cq * 4 + 3][d] * sc[cq * 4 + 3];
        reinterpret_cast<float4*>(&g_Pn2T[d * CPAD + c0])[cq] = o;  // pad rows write 0
    }
}

// ---------------------------------------------------------------------------
// K3: fused GEMM + exp + row-sum.
// Block tile: 64 rows (M) x 128 classes (N), K=64 resident. 256 threads,
// each owns 4 rows x 8 cols as 4x4 packed f32x2 accumulators.
// ---------------------------------------------------------------------------
__global__ void __launch_bounds__(256) gemm_kernel() {
    __shared__ __align__(16) float As[DIM][BM];   // 16 KB, k-major
    __shared__ __align__(16) float Bs[DIM][BN];   // 32 KB, k-major  (total = 48 KB)
    const int c0  = blockIdx.x * BN;
    const int m0  = blockIdx.y * BM;
    const int tid = threadIdx.x;

    // Conflict-free, fully coalesced tile loads (sources already k-major)
    #pragma unroll
    for (int it = 0; it < 4; ++it) {
        int g = tid + it * 256;                   // 1024 float4
        int k = g >> 4, mq = g & 15;
        reinterpret_cast<float4*>(&As[k][0])[mq] =
            reinterpret_cast<const float4*>(&g_xsT[k * BATCH + m0])[mq];
    }
    #pragma unroll
    for (int it = 0; it < 8; ++it) {
        int g = tid + it * 256;                   // 2048 float4
        int k = g >> 5, cq = g & 31;
        reinterpret_cast<float4*>(&Bs[k][0])[cq] =
            reinterpret_cast<const float4*>(&g_Pn2T[k * CPAD + c0])[cq];
    }
    __syncthreads();

    const int tx = tid & 15, ty = tid >> 4;       // tx -> N, ty -> M

    unsigned long long acc[4][4];
    #pragma unroll
    for (int r = 0; r < 4; ++r)
        #pragma unroll
        for (int q = 0; q < 4; ++q) acc[r][q] = 0ull;   // packed {0.f,0.f}

    #pragma unroll 8
    for (int k = 0; k < DIM; ++k) {
        float4 av = *reinterpret_cast<const float4*>(&As[k][ty * 4]);       // broadcast
        ulonglong2 b01 = *reinterpret_cast<const ulonglong2*>(&Bs[k][tx * 8]);
        ulonglong2 b23 = *reinterpret_cast<const ulonglong2*>(&Bs[k][tx * 8 + 4]);
        unsigned long long a0 = dup2(av.x), a1 = dup2(av.y);
        unsigned long long a2 = dup2(av.z), a3 = dup2(av.w);
        ffma2(acc[0][0], a0, b01.x); ffma2(acc[0][1], a0, b01.y);
        ffma2(acc[0][2], a0, b23.x); ffma2(acc[0][3], a0, b23.y);
        ffma2(acc[1][0], a1, b01.x); ffma2(acc[1][1], a1, b01.y);
        ffma2(acc[1][2], a1, b23.x); ffma2(acc[1][3], a1, b23.y);
        ffma2(acc[2][0], a2, b01.x); ffma2(acc[2][1], a2, b01.y);
        ffma2(acc[2][2], a2, b23.x); ffma2(acc[2][3], a2, b23.y);
        ffma2(acc[3][0], a3, b01.x); ffma2(acc[3][1], a3, b01.y);
        ffma2(acc[3][2], a3, b23.x); ffma2(acc[3][3], a3, b23.y);
    }

    // Fused epilogue: t = acc - 1 (factor 2 pre-folded), e = exp(t), row sums.
    // t in [-20, 18] always -> no max-shift needed; pad columns masked out.
    float rsum[4];
    #pragma unroll
    for (int r = 0; r < 4; ++r) {
        float s = 0.f;
        #pragma unroll
        for (int q = 0; q < 4; ++q) {
            int c = c0 + tx * 8 + q * 2;
            float lo = __uint_as_float((unsigned int)(acc[r][q] & 0xffffffffull));
            float hi = __uint_as_float((unsigned int)(acc[r][q] >> 32));
            if (c     < NB_C) s += __expf(lo - 1.0f);
            if (c + 1 < NB_C) s += __expf(hi - 1.0f);
        }
        rsum[r] = s;
    }
    // Reduce over the 16 tx lanes (stays inside each half-warp: offsets <= 8)
    #pragma unroll
    for (int off = 8; off >= 1; off >>= 1) {
        #pragma unroll
        for (int r = 0; r < 4; ++r)
            rsum[r] += __shfl_xor_sync(0xffffffffu, rsum[r], off);
    }
    if (tx == 0) {
        #pragma unroll
        for (int r = 0; r < 4; ++r)
            atomicAdd(&g_S[m0 + ty * 4 + r], rsum[r]);
    }
}

// ---------------------------------------------------------------------------
// K4: per-sample loss + mean.
// per_i = log(S_i - exp(t_pos)) - t_pos,  t_pos = x_i . Pn2[:,y_i] - 1.
// ys dtype is detected at runtime (int64 vs int32): int64 layout has every
// odd 32-bit word == 0 (labels < 2^31); 32 consecutive accidental zeros from
// random int32 labels is probability ~1e-160.
// ---------------------------------------------------------------------------
__global__ void final_kernel(const float* __restrict__ xs,
                             const int*   __restrict__ ysw,
                             float*       __restrict__ out) {
    __shared__ float red[1024];
    const int i = threadIdx.x;

    bool is64 = true;
    #pragma unroll
    for (int j = 1; j < 64; j += 2)
        if (ysw[j] != 0) is64 = false;
    int y = is64 ? ysw[2 * i] : ysw[i];          // little-endian low word

    const float4* xv = reinterpret_cast<const float4*>(xs + i * DIM);
    float dot = 0.f;
    #pragma unroll
    for (int dq = 0; dq < 16; ++dq) {
        float4 v = xv[dq];
        int d = dq * 4;
        dot += v.x * g_Pn2T[(d + 0) * CPAD + y];
        dot += v.y * g_Pn2T[(d + 1) * CPAD + y];
        dot += v.z * g_Pn2T[(d + 2) * CPAD + y];
        dot += v.w * g_Pn2T[(d + 3) * CPAD + y];
    }
    float tpos = dot - 1.0f;
    float per  = logf(g_S[i] - expf(tpos)) - tpos;

    red[i] = per;
    __syncthreads();
    for (int sft = 512; sft > 0; sft >>= 1) {
        if (i < sft) red[i] += red[i + sft];
        __syncthreads();
    }
    if (i == 0) out[0] = red[0] * (1.0f / 1024.0f);
}

// ---------------------------------------------------------------------------
// Launch: 4 kernels on the default stream, fully graph-capturable.
// Inputs bound by element count (order-independent): xs=65536, ys=1024,
// proxies=6400000.
// ---------------------------------------------------------------------------
extern "C" void kernel_launch(void* const* d_in, const int* in_sizes, int n_in,
                              void* d_out, int out_size) {
    const float* xs      = nullptr;
    const int*   ys      = nullptr;
    const float* proxies = nullptr;
    for (int i = 0; i < n_in; ++i) {
        if      (in_sizes[i] == BATCH * DIM) xs      = (const float*)d_in[i];
        else if (in_sizes[i] == BATCH)       ys      = (const int*)d_in[i];
        else if (in_sizes[i] == NB_C * DIM)  proxies = (const float*)d_in[i];
    }
    (void)out_size;

    prep_kernel <<<(BATCH * DIM) / 256, 256>>>(xs);
    norm_kernel <<<CPAD / 64, 256>>>(proxies);
    gemm_kernel <<<dim3(CPAD / BN, BATCH / BM), 256>>>();
    final_kernel<<<1, 1024>>>(xs, ys, (float*)d_out);
}

// round 12
// speedup vs baseline: 3.7857x; 3.7857x over previous
#include <cuda_runtime.h>
#include <cuda_bf16.h>
#include <cstdint>
#include <math.h>

// ---------------------------------------------------------------------------
// Problem constants
// ---------------------------------------------------------------------------
#define NB_C   100000
#define DIM    64
#define BATCH  1024
#define BM     128
#define BN     128
#define NT     782                 // ceil(100000/128)
#define MT     8                   // 1024/128
#define CPAD   (NT * BN)           // 100096, pad rows zero
#define NBLK   (NT * MT)           // 6256 CTAs
#define PITCH  72                  // smem row pitch in bf16 (144 B): LDSM conflict-free

// ---------------------------------------------------------------------------
// Device scratch
// ---------------------------------------------------------------------------
__device__ __nv_bfloat16 g_Xh[BATCH * DIM];
__device__ __nv_bfloat16 g_Xl[BATCH * DIM];
__device__ __nv_bfloat16 g_Ph[CPAD * DIM];   // 2*p/||p||, hi part, row-major [class][dim]
__device__ __nv_bfloat16 g_Pl[CPAD * DIM];   // lo part
__device__ float         g_S  [BATCH];       // S_i = sum_c exp(t_ic - 1)  (incl. pad)
__device__ float         g_per[BATCH];

// ---------------------------------------------------------------------------
// PTX helpers (sm_80-generic only: ldmatrix + mma.sync — legal on sm_103)
// ---------------------------------------------------------------------------
__device__ __forceinline__ uint32_t smem_u32(const void* p) {
    uint32_t a;
    asm("{ .reg .u64 t; cvta.to.shared.u64 t, %1; cvt.u32.u64 %0, t; }"
        : "=r"(a) : "l"(p));
    return a;
}
__device__ __forceinline__ void ldsm4(uint32_t& r0, uint32_t& r1,
                                      uint32_t& r2, uint32_t& r3, uint32_t addr) {
    asm volatile("ldmatrix.sync.aligned.m8n8.x4.shared.b16 {%0,%1,%2,%3}, [%4];"
        : "=r"(r0), "=r"(r1), "=r"(r2), "=r"(r3) : "r"(addr));
}
__device__ __forceinline__ void mma_bf16(float* c, const uint32_t* a,
                                         uint32_t b0, uint32_t b1) {
    asm volatile(
        "mma.sync.aligned.m16n8k16.row.col.f32.bf16.bf16.f32 "
        "{%0,%1,%2,%3}, {%4,%5,%6,%7}, {%8,%9}, {%0,%1,%2,%3};"
        : "+f"(c[0]), "+f"(c[1]), "+f"(c[2]), "+f"(c[3])
        : "r"(a[0]), "r"(a[1]), "r"(a[2]), "r"(a[3]), "r"(b0), "r"(b1));
}

// ---------------------------------------------------------------------------
// K1: split xs into bf16 hi/lo, zero g_S
// ---------------------------------------------------------------------------
__global__ void prep_kernel(const float* __restrict__ xs) {
    int g = blockIdx.x * 256 + threadIdx.x;          // 0..65535
    float x = xs[g];
    __nv_bfloat16 h = __float2bfloat16(x);
    __nv_bfloat16 l = __float2bfloat16(x - __bfloat162float(h));
    g_Xh[g] = h; g_Xl[g] = l;
    if (g < BATCH) g_S[g] = 0.0f;
}

// ---------------------------------------------------------------------------
// K2: per-proxy-row L2-normalize (x2 folded), split to bf16 hi/lo. 1 warp/row.
// Pad rows (>= NB_C) write exact zeros.
// ---------------------------------------------------------------------------
__global__ void norm_kernel(const float* __restrict__ proxies) {
    int gw   = (blockIdx.x * 256 + threadIdx.x) >> 5;    // row 0..CPAD-1
    int lane = threadIdx.x & 31;
    if (gw >= CPAD) return;
    float2 v = make_float2(0.f, 0.f);
    if (gw < NB_C) v = reinterpret_cast<const float2*>(proxies)[gw * 32 + lane];
    float ss = v.x * v.x + v.y * v.y;
    #pragma unroll
    for (int off = 16; off >= 1; off >>= 1) ss += __shfl_xor_sync(0xffffffffu, ss, off);
    float sc = 2.0f / fmaxf(sqrtf(ss), 1e-12f);
    float a = v.x * sc, b = v.y * sc;
    __nv_bfloat16 ah = __float2bfloat16(a);
    __nv_bfloat16 al = __float2bfloat16(a - __bfloat162float(ah));
    __nv_bfloat16 bh = __float2bfloat16(b);
    __nv_bfloat16 bl = __float2bfloat16(b - __bfloat162float(bh));
    __nv_bfloat162 hv; hv.x = ah; hv.y = bh;
    __nv_bfloat162 lv; lv.x = al; lv.y = bl;
    reinterpret_cast<__nv_bfloat162*>(g_Ph)[gw * 32 + lane] = hv;
    reinterpret_cast<__nv_bfloat162*>(g_Pl)[gw * 32 + lane] = lv;
}

// ---------------------------------------------------------------------------
// K3: GEMM via mma.sync bf16 (register accumulators) + fused exp/row-sum.
// CTA tile 128x128, K=64 resident. 8 warps, each 32(M) x 64(N).
// Per warp per k16-step: 2 A-blocks x 8 B-blocks x 3 splits = 48 mma.
// ---------------------------------------------------------------------------
#define OFF_AH 0
#define OFF_AL (BM * PITCH * 2)            // 18432
#define OFF_BH (2 * BM * PITCH * 2)        // 36864
#define OFF_BL (3 * BM * PITCH * 2)        // 55296
#define SMEM_BYTES (4 * BM * PITCH * 2)    // 73728

__global__ void __launch_bounds__(256, 1) gemm_kernel() {
    extern __shared__ __align__(16) char sm[];
    const uint32_t sb = smem_u32(sm);
    const int tid = threadIdx.x, wid = tid >> 5, lane = tid & 31;
    const int mt = blockIdx.x & 7, nt = blockIdx.x >> 3;   // mt fastest: B reused in L2

    // -- load tiles (row = 128B of data in 144B pitch; coalesced gmem, conflict-free STS)
    {
        const uint4* sAH = reinterpret_cast<const uint4*>(g_Xh) + (size_t)mt * BM * 8;
        const uint4* sAL = reinterpret_cast<const uint4*>(g_Xl) + (size_t)mt * BM * 8;
        const uint4* sBH = reinterpret_cast<const uint4*>(g_Ph) + (size_t)nt * BN * 8;
        const uint4* sBL = reinterpret_cast<const uint4*>(g_Pl) + (size_t)nt * BN * 8;
        #pragma unroll
        for (int it = 0; it < 4; ++it) {
            int g = tid + it * 256;               // 1024 chunks per matrix
            int row = g >> 3, ch = g & 7;
            int off = row * (PITCH * 2) + ch * 16;
            *reinterpret_cast<uint4*>(sm + OFF_AH + off) = sAH[g];
            *reinterpret_cast<uint4*>(sm + OFF_AL + off) = sAL[g];
            *reinterpret_cast<uint4*>(sm + OFF_BH + off) = sBH[g];
            *reinterpret_cast<uint4*>(sm + OFF_BL + off) = sBL[g];
        }
    }
    __syncthreads();

    const int wm = (wid & 3) * 32;      // warp M offset (4 warps along M)
    const int wn = (wid >> 2) * 64;     // warp N offset (2 warps along N)
    const int r  = lane & 7, q = lane >> 3;

    // ldmatrix address bases (per-thread), byte offsets into smem
    // A x4 matrices: q0:(r,k0) q1:(8+r,k0) q2:(r,k8) q3:(8+r,k8)
    const uint32_t aRow = wm + r + (q & 1) * 8;
    const uint32_t aOff = aRow * (PITCH * 2) + (q >> 1) * 16;
    // B x4 matrices: q0:(n r,k0)->b0 even, q1:(n r,k8)->b1 even, q2:(n 8+r,k0), q3:(n 8+r,k8)
    const uint32_t bRow = wn + r + (q >> 1) * 8;
    const uint32_t bOff = bRow * (PITCH * 2) + (q & 1) * 16;

    float c[2][8][4];
    #pragma unroll
    for (int mb = 0; mb < 2; ++mb)
        #pragma unroll
        for (int nb = 0; nb < 8; ++nb)
            #pragma unroll
            for (int e = 0; e < 4; ++e) c[mb][nb][e] = 0.f;

    #pragma unroll
    for (int ks = 0; ks < 4; ++ks) {                      // K = 4 x k16
        const uint32_t kb = ks * 32;                      // 16 bf16 = 32 B
        uint32_t ah[2][4], al[2][4];
        #pragma unroll
        for (int mb = 0; mb < 2; ++mb) {
            uint32_t base = sb + aOff + mb * 16 * (PITCH * 2) + kb;
            ldsm4(ah[mb][0], ah[mb][1], ah[mb][2], ah[mb][3], base + OFF_AH);
            ldsm4(al[mb][0], al[mb][1], al[mb][2], al[mb][3], base + OFF_AL);
        }
        uint32_t bh[4][4], bl[4][4];
        #pragma unroll
        for (int np = 0; np < 4; ++np) {                  // pair of n8 blocks
            uint32_t base = sb + bOff + np * 16 * (PITCH * 2) + kb;
            ldsm4(bh[np][0], bh[np][1], bh[np][2], bh[np][3], base + OFF_BH);
            ldsm4(bl[np][0], bl[np][1], bl[np][2], bl[np][3], base + OFF_BL);
        }
        #pragma unroll
        for (int mb = 0; mb < 2; ++mb)
            #pragma unroll
            for (int np = 0; np < 4; ++np)
                #pragma unroll
                for (int h = 0; h < 2; ++h) {
                    int nb = np * 2 + h;
                    mma_bf16(c[mb][nb], ah[mb], bh[np][h * 2], bh[np][h * 2 + 1]);
                    mma_bf16(c[mb][nb], ah[mb], bl[np][h * 2], bl[np][h * 2 + 1]);
                    mma_bf16(c[mb][nb], al[mb], bh[np][h * 2], bh[np][h * 2 + 1]);
                }
    }

    // -- fused epilogue: t = c - 1, e = exp(t), row sums (pad cols give e^-1;
    //    removed analytically in final1). Quad-reduce then atomicAdd per row.
    const int g = lane >> 2;
    #pragma unroll
    for (int mb = 0; mb < 2; ++mb) {
        float sA = 0.f, sB = 0.f;
        #pragma unroll
        for (int nb = 0; nb < 8; ++nb) {
            sA += __expf(c[mb][nb][0] - 1.0f) + __expf(c[mb][nb][1] - 1.0f);
            sB += __expf(c[mb][nb][2] - 1.0f) + __expf(c[mb][nb][3] - 1.0f);
        }
        sA += __shfl_xor_sync(0xffffffffu, sA, 1);
        sA += __shfl_xor_sync(0xffffffffu, sA, 2);
        sB += __shfl_xor_sync(0xffffffffu, sB, 1);
        sB += __shfl_xor_sync(0xffffffffu, sB, 2);
        if ((lane & 3) == 0) {
            int row = mt * BM + wm + mb * 16 + g;
            atomicAdd(&g_S[row],     sA);
            atomicAdd(&g_S[row + 8], sB);
        }
    }
}

// ---------------------------------------------------------------------------
// K4: per-sample loss, 1 warp/sample. Subtract pad contribution (96 * e^-1).
// ys dtype (int64 vs int32) detected per-warp via ballot over odd words.
// ---------------------------------------------------------------------------
__global__ void final1_kernel(const int* __restrict__ ysw) {
    int s    = (blockIdx.x * 256 + threadIdx.x) >> 5;   // sample 0..1023
    int lane = threadIdx.x & 31;
    unsigned bal = __ballot_sync(0xffffffffu, ysw[2 * lane + 1] != 0);
    int y = (bal == 0u) ? ysw[2 * s] : ysw[s];

    __nv_bfloat162 xh = reinterpret_cast<const __nv_bfloat162*>(g_Xh)[s * 32 + lane];
    __nv_bfloat162 xl = reinterpret_cast<const __nv_bfloat162*>(g_Xl)[s * 32 + lane];
    __nv_bfloat162 ph = reinterpret_cast<const __nv_bfloat162*>(g_Ph)[y * 32 + lane];
    __nv_bfloat162 pl = reinterpret_cast<const __nv_bfloat162*>(g_Pl)[y * 32 + lane];
    float x0 = __bfloat162float(xh.x) + __bfloat162float(xl.x);
    float x1 = __bfloat162float(xh.y) + __bfloat162float(xl.y);
    float p0 = __bfloat162float(ph.x) + __bfloat162float(pl.x);
    float p1 = __bfloat162float(ph.y) + __bfloat162float(pl.y);
    float dot = x0 * p0 + x1 * p1;
    #pragma unroll
    for (int off = 16; off >= 1; off >>= 1) dot += __shfl_xor_sync(0xffffffffu, dot, off);
    if (lane == 0) {
        float tpos = dot - 1.0f;
        float S = g_S[s] - (float)(CPAD - NB_C) * expf(-1.0f);  // remove pad classes
        g_per[s] = logf(S - expf(tpos)) - tpos;
    }
}

__global__ void final2_kernel(float* __restrict__ out) {
    __shared__ float red[1024];
    int i = threadIdx.x;
    red[i] = g_per[i];
    __syncthreads();
    for (int sft = 512; sft > 0; sft >>= 1) {
        if (i < sft) red[i] += red[i + sft];
        __syncthreads();
    }
    if (i == 0) out[0] = red[0] * (1.0f / 1024.0f);
}

// ---------------------------------------------------------------------------
// Launch (graph-capturable: kernel launches only)
// ---------------------------------------------------------------------------
extern "C" void kernel_launch(void* const* d_in, const int* in_sizes, int n_in,
                              void* d_out, int out_size) {
    const float* xs = nullptr; const int* ys = nullptr; const float* proxies = nullptr;
    for (int i = 0; i < n_in; ++i) {
        if      (in_sizes[i] == BATCH * DIM) xs      = (const float*)d_in[i];
        else if (in_sizes[i] == BATCH)       ys      = (const int*)d_in[i];
        else if (in_sizes[i] == NB_C * DIM)  proxies = (const float*)d_in[i];
    }
    (void)out_size;

    cudaFuncSetAttribute(gemm_kernel, cudaFuncAttributeMaxDynamicSharedMemorySize,
                         SMEM_BYTES);

    prep_kernel  <<<(BATCH * DIM) / 256, 256>>>(xs);
    norm_kernel  <<<CPAD / 8, 256>>>(proxies);
    gemm_kernel  <<<NBLK, 256, SMEM_BYTES>>>();
    final1_kernel<<<128, 256>>>(ys);
    final2_kernel<<<1, 1024>>>((float*)d_out);
}